// round 16
// baseline (speedup 1.0000x reference)
#include <cuda_runtime.h>

// Fan-beam CT forward projector — two-phase bin-pair gather.
// Main kernel inner loop: FIXED 5 perpendicular slots per driving step
// (provable: pair-wedge perp span <= 4.64 px < 5), no predicates, no tail.
constexpr int   R_      = 384;
constexpr int   C_      = 384;
constexpr int   NCOLS_  = 768;
constexpr int   V_      = 256;
constexpr float DR_     = 1.0f;
constexpr float DC_     = 1.0f;
constexpr float DSPACE_ = 1.5f;

constexpr int WARPS_PER_BLOCK = 4;
constexpr int NPAIRS = NCOLS_ / 2;     // 384
constexpr int NWORK  = V_ * NPAIRS;    // 98304

// per-(view,pair): [0]=(q0,qs,qp,b0) [1]=(bs,bp,alo-.01,blo)
__device__ float4 g_pre[NWORK * 2];
// packed window: w0i | w1i<<10 | drive_c<<20   (all fields small, >=0)
__device__ int    g_win[NWORK];

__device__ __forceinline__ void drive_window(float ahi, float bhi,
                                             float alo, float blo,
                                             int& w0, int& w1)
{
    float f0 = 0.0f, f1 = 383.0f;
    const float eps = 1e-12f;
    if (bhi > eps)        f0 = fmaxf(f0, __fdividef(-0.01f - ahi, bhi) - 1.0f);
    else if (bhi < -eps)  f1 = fminf(f1, __fdividef(-0.01f - ahi, bhi) + 1.0f);
    else if (ahi < -0.01f) { w0 = 1; w1 = 0; return; }
    const float L = 383.01f;
    if (blo > eps)        f1 = fminf(f1, __fdividef(L - alo, blo) + 1.0f);
    else if (blo < -eps)  f0 = fmaxf(f0, __fdividef(L - alo, blo) - 1.0f);
    else if (alo > L)     { w0 = 1; w1 = 0; return; }
    w0 = max(0, __float2int_ru(f0));
    w1 = min(383, __float2int_rd(f1));
}

__global__ void setup_kernel(const float* __restrict__ src_g,
                             const float* __restrict__ detc_g,
                             const float* __restrict__ u_g,
                             const float* __restrict__ center_g,
                             const float* __restrict__ cdir_g)
{
    const int idx = blockIdx.x * blockDim.x + threadIdx.x;
    if (idx >= NWORK) return;
    const int v    = idx / NPAIRS;
    const int pair = idx - v * NPAIRS;
    const int ib   = pair * 2;

    const float sx  = src_g [2*v+0], sy  = src_g [2*v+1];
    const float dcx = detc_g[2*v+0], dcy = detc_g[2*v+1];
    const float ux  = u_g  [2*v+0], uy  = u_g  [2*v+1];
    const float nx  = -uy,          ny  = ux;
    const float cx  = center_g[0],  cy  = center_g[1];
    const float colx = cdir_g[0],   coly = cdir_g[1];
    const float rowx = -coly,       rowy = colx;

    const float vzx = cx - 0.5f*(R_-1)*DR_*rowx - 0.5f*(C_-1)*DC_*colx;
    const float vzy = cy - 0.5f*(R_-1)*DR_*rowy - 0.5f*(C_-1)*DC_*coly;

    const float src_d = sx*nx + sy*ny;
    const float su    = sx*ux + sy*uy;
    const float K     = (dcx*nx + dcy*ny) - src_d;
    const float h     = 0.5f*(NCOLS_-1)*DSPACE_;
    const float dzx   = dcx - h*ux, dzy = dcy - h*uy;
    const float A     = su - (dzx*ux + dzy*uy);

    const float bn0 = vzx*nx + vzy*ny - src_d;
    const float dnr = DR_*(rowx*nx + rowy*ny);
    const float dnc = DC_*(colx*nx + coly*ny);
    const float bu0 = vzx*ux + vzy*uy - su;
    const float dur = DR_*(rowx*ux + rowy*uy);
    const float duc = DC_*(colx*ux + coly*uy);

    const float den_c = bn0 + 0.5f*(R_-1)*dnr + 0.5f*(C_-1)*dnc;
    const float sig   = (den_c > 0.0f) ? 1.0f : -1.0f;
    const bool  tok   = (sig * K) > 0.0f;

    const float E  = A - (float)ib * DSPACE_;
    const float q0 = sig * (E*bn0 + K*bu0);
    const float qr = sig * (E*dnr + K*dur);
    const float qc = sig * (E*dnc + K*duc);
    const float b0 = sig * DSPACE_ * bn0;
    const float br = sig * DSPACE_ * dnr;
    const float bc = sig * DSPACE_ * dnc;

    const float ic_f = (float)ib + 0.5f;
    const float bxp = dzx + ic_f*DSPACE_*ux - sx;
    const float byp = dzy + ic_f*DSPACE_*uy - sy;
    const float dc_comp = bxp*colx + byp*coly;
    const float dr_comp = bxp*rowx + byp*rowy;
    const bool  drive_c = fabsf(dc_comp) >= fabsf(dr_comp);

    const float qs = drive_c ? qc : qr;
    const float qp = drive_c ? qr : qc;
    const float bs = drive_c ? bc : br;
    const float bp = drive_c ? br : bc;

    // pair wedge lines: Q + B = 0 (col = ib-1), Q - 2B = 0 (col = ib+2)
    const float gm  = qp + bp;
    const float gp2 = qp - 2.0f*bp;
    const float am  = __fdividef(-(q0 + b0),      gm);
    const float bm  = __fdividef(-(qs + bs),      gm);
    const float ap  = __fdividef(-(q0 - 2.0f*b0), gp2);
    const float bp3 = __fdividef(-(qs - 2.0f*bs), gp2);
    float alo, blo, ahi, bhi;
    if (fmaf(191.5f, bm, am) <= fmaf(191.5f, bp3, ap)) {
        alo = am; blo = bm; ahi = ap; bhi = bp3;
    } else {
        alo = ap; blo = bp3; ahi = am; bhi = bm;
    }

    int w0i, w1i;
    if (tok) drive_window(ahi, bhi, alo, blo, w0i, w1i);
    else     { w0i = 1; w1i = 0; }
    if (w1i < w0i) { w0i = 1; w1i = 0; }   // canonical empty, fields >= 0

    float4* o = g_pre + idx * 2;
    o[0] = make_float4(q0, qs, qp, b0);
    o[1] = make_float4(bs, bp, alo - 0.01f, blo);   // margin baked into alo
    g_win[idx] = w0i | (w1i << 10) | (drive_c ? (1 << 20) : 0);
}

// Walk driving coordinate s (lanes strided by 32); perp coord p with
// compile-time stride PSTR; SROW is the complementary stride.
// FIXED 5 slots: all w>0 pixels provably inside [p0, p0+4]; extra slots
// have w <= 0 and are annihilated by fmaxf. All addresses in-bounds.
template<int PSTR, int SROW>
__device__ __forceinline__ void walk(const float* __restrict__ img,
                                     int lane, int w0i, int w1i,
                                     float q0, float qs, float qp,
                                     float b0, float bs, float bp,
                                     float alo_m, float blo,
                                     float& acc0, float& acc1)
{
    const float* srow = img + (w0i + lane) * SROW;   // advances by 32*SROW
    for (int s = w0i + lane; s <= w1i; s += 32, srow += 32 * SROW) {
        const float sf  = (float)s;
        const float plo = fmaf(sf, blo, alo_m);
        const float pf0 = fminf(fmaxf(ceilf(plo), 0.0f), 379.0f);
        const int   p0  = (int)pf0;
        const float Qb  = fmaf(pf0, qp, fmaf(sf, qs, q0));
        const float Bb  = fmaf(pf0, bp, fmaf(sf, bs, b0));
        const float* p  = srow + p0 * PSTR;
        #pragma unroll
        for (int k = 0; k < 5; ++k) {
            const float Qp = fmaf((float)k, qp, Qb);
            const float Bp = fmaf((float)k, bp, Bb);
            const float rb = __fdividef(1.0f, Bp);
            const float val = __ldg(p + k*PSTR);
            const float wA = fmaf(-fabsf(Qp), rb, 1.0f);
            const float wB = fmaf(-fabsf(Qp - Bp), rb, 1.0f);
            acc0 = fmaf(fmaxf(wA, 0.0f), val, acc0);
            acc1 = fmaf(fmaxf(wB, 0.0f), val, acc1);
        }
    }
}

__global__ __launch_bounds__(32 * WARPS_PER_BLOCK, 12)
void fanbeam_fp_kernel(const float* __restrict__ img,
                       float* __restrict__ sino)
{
    const int v    = blockIdx.y;
    const int warp = threadIdx.x >> 5;
    const int lane = threadIdx.x & 31;
    const int pair = blockIdx.x * WARPS_PER_BLOCK + warp;   // adjacent pairs
    const int ib   = pair * 2;
    const int idx  = v * NPAIRS + pair;

    const float4* pp = g_pre + idx * 2;
    const float4 A0 = __ldg(pp + 0);
    const float4 A1 = __ldg(pp + 1);
    const int    wn = __ldg(g_win + idx);

    const float q0 = A0.x, qs = A0.y, qp = A0.z, b0 = A0.w;
    const float bs = A1.x, bp = A1.y, alo_m = A1.z, blo = A1.w;
    const int   w0i     = wn & 0x3FF;
    const int   w1i     = (wn >> 10) & 0x3FF;
    const bool  drive_c = (wn >> 20) != 0;

    float acc0 = 0.0f, acc1 = 0.0f;

    if (w0i <= w1i) {
        if (drive_c)
            walk<C_, 1>(img, lane, w0i, w1i, q0, qs, qp, b0, bs, bp,
                        alo_m, blo, acc0, acc1);
        else
            walk<1, C_>(img, lane, w0i, w1i, q0, qs, qp, b0, bs, bp,
                        alo_m, blo, acc0, acc1);
    }

    #pragma unroll
    for (int off = 16; off > 0; off >>= 1) {
        acc0 += __shfl_xor_sync(0xffffffffu, acc0, off);
        acc1 += __shfl_xor_sync(0xffffffffu, acc1, off);
    }

    if (lane == 0) {
        sino[v*NCOLS_ + ib]     = acc0;
        sino[v*NCOLS_ + ib + 1] = acc1;
    }
}

extern "C" void kernel_launch(void* const* d_in, const int* in_sizes, int n_in,
                              void* d_out, int out_size)
{
    const float* img    = (const float*)d_in[0];
    const float* src    = (const float*)d_in[1];
    const float* detc   = (const float*)d_in[2];
    const float* u      = (const float*)d_in[3];
    const float* center = (const float*)d_in[4];
    const float* cdir   = (const float*)d_in[5];
    float* sino = (float*)d_out;

    setup_kernel<<<(NWORK + 255) / 256, 256>>>(src, detc, u, center, cdir);

    dim3 grid(NPAIRS / WARPS_PER_BLOCK, V_);
    dim3 block(32 * WARPS_PER_BLOCK);
    fanbeam_fp_kernel<<<grid, block>>>(img, sino);
}

// round 17
// speedup vs baseline: 1.4054x; 1.4054x over previous
#include <cuda_runtime.h>

// Fan-beam CT forward projector — two-phase bin-pair gather.
// Setup computes exact per-(view,pair) max perpendicular span -> nslots;
// main kernel dispatches warp-uniformly to an nslots-specialized walk
// (predicated slots gate both ALU and LDG; tail loop as safety net).
constexpr int   R_      = 384;
constexpr int   C_      = 384;
constexpr int   NCOLS_  = 768;
constexpr int   V_      = 256;
constexpr float DR_     = 1.0f;
constexpr float DC_     = 1.0f;
constexpr float DSPACE_ = 1.5f;

constexpr int WARPS_PER_BLOCK = 4;
constexpr int NPAIRS = NCOLS_ / 2;     // 384
constexpr int NWORK  = V_ * NPAIRS;    // 98304

// per-(view,pair): [0]=(q0,qs,qp,b0) [1]=(bs,bp,alo-.01,blo) [2]=(ahi+.01,bhi,-,-)
__device__ float4 g_pre[NWORK * 3];
// packed: w0i | w1i<<10 | drive_c<<20 | nslots<<21
__device__ int    g_win[NWORK];

__device__ __forceinline__ void drive_window(float ahi, float bhi,
                                             float alo, float blo,
                                             int& w0, int& w1)
{
    float f0 = 0.0f, f1 = 383.0f;
    const float eps = 1e-12f;
    if (bhi > eps)        f0 = fmaxf(f0, __fdividef(-0.01f - ahi, bhi) - 1.0f);
    else if (bhi < -eps)  f1 = fminf(f1, __fdividef(-0.01f - ahi, bhi) + 1.0f);
    else if (ahi < -0.01f) { w0 = 1; w1 = 0; return; }
    const float L = 383.01f;
    if (blo > eps)        f1 = fminf(f1, __fdividef(L - alo, blo) + 1.0f);
    else if (blo < -eps)  f0 = fmaxf(f0, __fdividef(L - alo, blo) - 1.0f);
    else if (alo > L)     { w0 = 1; w1 = 0; return; }
    w0 = max(0, __float2int_ru(f0));
    w1 = min(383, __float2int_rd(f1));
}

__global__ void setup_kernel(const float* __restrict__ src_g,
                             const float* __restrict__ detc_g,
                             const float* __restrict__ u_g,
                             const float* __restrict__ center_g,
                             const float* __restrict__ cdir_g)
{
    const int idx = blockIdx.x * blockDim.x + threadIdx.x;
    if (idx >= NWORK) return;
    const int v    = idx / NPAIRS;
    const int pair = idx - v * NPAIRS;
    const int ib   = pair * 2;

    const float sx  = src_g [2*v+0], sy  = src_g [2*v+1];
    const float dcx = detc_g[2*v+0], dcy = detc_g[2*v+1];
    const float ux  = u_g  [2*v+0], uy  = u_g  [2*v+1];
    const float nx  = -uy,          ny  = ux;
    const float cx  = center_g[0],  cy  = center_g[1];
    const float colx = cdir_g[0],   coly = cdir_g[1];
    const float rowx = -coly,       rowy = colx;

    const float vzx = cx - 0.5f*(R_-1)*DR_*rowx - 0.5f*(C_-1)*DC_*colx;
    const float vzy = cy - 0.5f*(R_-1)*DR_*rowy - 0.5f*(C_-1)*DC_*coly;

    const float src_d = sx*nx + sy*ny;
    const float su    = sx*ux + sy*uy;
    const float K     = (dcx*nx + dcy*ny) - src_d;
    const float h     = 0.5f*(NCOLS_-1)*DSPACE_;
    const float dzx   = dcx - h*ux, dzy = dcy - h*uy;
    const float A     = su - (dzx*ux + dzy*uy);

    const float bn0 = vzx*nx + vzy*ny - src_d;
    const float dnr = DR_*(rowx*nx + rowy*ny);
    const float dnc = DC_*(colx*nx + coly*ny);
    const float bu0 = vzx*ux + vzy*uy - su;
    const float dur = DR_*(rowx*ux + rowy*uy);
    const float duc = DC_*(colx*ux + coly*uy);

    const float den_c = bn0 + 0.5f*(R_-1)*dnr + 0.5f*(C_-1)*dnc;
    const float sig   = (den_c > 0.0f) ? 1.0f : -1.0f;
    const bool  tok   = (sig * K) > 0.0f;

    const float E  = A - (float)ib * DSPACE_;
    const float q0 = sig * (E*bn0 + K*bu0);
    const float qr = sig * (E*dnr + K*dur);
    const float qc = sig * (E*dnc + K*duc);
    const float b0 = sig * DSPACE_ * bn0;
    const float br = sig * DSPACE_ * dnr;
    const float bc = sig * DSPACE_ * dnc;

    const float ic_f = (float)ib + 0.5f;
    const float bxp = dzx + ic_f*DSPACE_*ux - sx;
    const float byp = dzy + ic_f*DSPACE_*uy - sy;
    const float dc_comp = bxp*colx + byp*coly;
    const float dr_comp = bxp*rowx + byp*rowy;
    const bool  drive_c = fabsf(dc_comp) >= fabsf(dr_comp);

    const float qs = drive_c ? qc : qr;
    const float qp = drive_c ? qr : qc;
    const float bs = drive_c ? bc : br;
    const float bp = drive_c ? br : bc;

    // pair wedge lines: Q + B = 0 (col = ib-1), Q - 2B = 0 (col = ib+2)
    const float gm  = qp + bp;
    const float gp2 = qp - 2.0f*bp;
    const float am  = __fdividef(-(q0 + b0),      gm);
    const float bm  = __fdividef(-(qs + bs),      gm);
    const float ap  = __fdividef(-(q0 - 2.0f*b0), gp2);
    const float bp3 = __fdividef(-(qs - 2.0f*bs), gp2);
    float alo, blo, ahi, bhi;
    if (fmaf(191.5f, bm, am) <= fmaf(191.5f, bp3, ap)) {
        alo = am; blo = bm; ahi = ap; bhi = bp3;
    } else {
        alo = ap; blo = bp3; ahi = am; bhi = bm;
    }

    int w0i, w1i;
    if (tok) drive_window(ahi, bhi, alo, blo, w0i, w1i);
    else     { w0i = 1; w1i = 0; }
    if (w1i < w0i) { w0i = 1; w1i = 0; }   // canonical empty, fields >= 0

    // exact max perpendicular span over the window (span(s) linear in s)
    const float da = ahi - alo, db = bhi - blo;
    const float sp0 = da + db * (float)w0i;
    const float sp1 = da + db * (float)w1i;
    const float span_max = fmaxf(fmaxf(sp0, sp1), 0.0f);
    int nslots = (int)ceilf(span_max + 0.021f) + 1;
    nslots = min(5, max(1, nslots));

    float4* o = g_pre + idx * 3;
    o[0] = make_float4(q0, qs, qp, b0);
    o[1] = make_float4(bs, bp, alo - 0.01f, blo);     // margin baked
    o[2] = make_float4(ahi + 0.01f, bhi, 0.0f, 0.0f); // margin baked
    g_win[idx] = w0i | (w1i << 10) | (drive_c ? (1 << 20) : 0) | (nslots << 21);
}

// Walk with NSLOTS predicated slots (+ safety tail). Predicates gate LDGs.
template<int PSTR, int SROW, int NSLOTS>
__device__ __forceinline__ void walk(const float* __restrict__ img,
                                     int lane, int w0i, int w1i,
                                     float q0, float qs, float qp,
                                     float b0, float bs, float bp,
                                     float alo_m, float blo,
                                     float ahi_m, float bhi,
                                     float& acc0, float& acc1)
{
    const float* srow = img + (w0i + lane) * SROW;   // advances by 32*SROW
    for (int s = w0i + lane; s <= w1i; s += 32, srow += 32 * SROW) {
        const float sf  = (float)s;
        const float plo = fmaxf(fmaf(sf, blo, alo_m), 0.0f);
        const float phi = fminf(fmaf(sf, bhi, ahi_m), 383.0f);
        const int p0 = __float2int_ru(plo);
        const int n  = __float2int_rd(phi) - p0;
        if (n >= 0) {
            const float pf0 = (float)p0;
            const float Qb  = fmaf(pf0, qp, fmaf(sf, qs, q0));
            const float Bb  = fmaf(pf0, bp, fmaf(sf, bs, b0));
            const float* p  = srow + p0 * PSTR;
            #pragma unroll
            for (int k = 0; k < NSLOTS; ++k) {
                if (k <= n) {
                    const float Qp = fmaf((float)k, qp, Qb);
                    const float Bp = fmaf((float)k, bp, Bb);
                    const float rb = __fdividef(1.0f, Bp);
                    const float val = __ldg(p + k*PSTR);
                    const float wA = fmaf(-fabsf(Qp), rb, 1.0f);
                    const float wB = fmaf(-fabsf(Qp - Bp), rb, 1.0f);
                    acc0 = fmaf(fmaxf(wA, 0.0f), val, acc0);
                    acc1 = fmaf(fmaxf(wB, 0.0f), val, acc1);
                }
            }
            for (int k = NSLOTS; k <= n; ++k) {     // safety tail (cold)
                const float Qp = fmaf((float)k, qp, Qb);
                const float Bp = fmaf((float)k, bp, Bb);
                const float rb = __fdividef(1.0f, Bp);
                const float val = __ldg(p + k*PSTR);
                const float wA = fmaf(-fabsf(Qp), rb, 1.0f);
                const float wB = fmaf(-fabsf(Qp - Bp), rb, 1.0f);
                acc0 = fmaf(fmaxf(wA, 0.0f), val, acc0);
                acc1 = fmaf(fmaxf(wB, 0.0f), val, acc1);
            }
        }
    }
}

template<int PSTR, int SROW>
__device__ __forceinline__ void walk_dispatch(const float* __restrict__ img,
                                              int lane, int w0i, int w1i, int nslots,
                                              float q0, float qs, float qp,
                                              float b0, float bs, float bp,
                                              float alo_m, float blo,
                                              float ahi_m, float bhi,
                                              float& acc0, float& acc1)
{
    switch (nslots) {
    case 1: walk<PSTR, SROW, 1>(img, lane, w0i, w1i, q0, qs, qp, b0, bs, bp,
                                alo_m, blo, ahi_m, bhi, acc0, acc1); break;
    case 2: walk<PSTR, SROW, 2>(img, lane, w0i, w1i, q0, qs, qp, b0, bs, bp,
                                alo_m, blo, ahi_m, bhi, acc0, acc1); break;
    case 3: walk<PSTR, SROW, 3>(img, lane, w0i, w1i, q0, qs, qp, b0, bs, bp,
                                alo_m, blo, ahi_m, bhi, acc0, acc1); break;
    case 4: walk<PSTR, SROW, 4>(img, lane, w0i, w1i, q0, qs, qp, b0, bs, bp,
                                alo_m, blo, ahi_m, bhi, acc0, acc1); break;
    default: walk<PSTR, SROW, 5>(img, lane, w0i, w1i, q0, qs, qp, b0, bs, bp,
                                 alo_m, blo, ahi_m, bhi, acc0, acc1); break;
    }
}

__global__ __launch_bounds__(32 * WARPS_PER_BLOCK, 12)
void fanbeam_fp_kernel(const float* __restrict__ img,
                       float* __restrict__ sino)
{
    const int v    = blockIdx.y;
    const int warp = threadIdx.x >> 5;
    const int lane = threadIdx.x & 31;
    const int pair = blockIdx.x * WARPS_PER_BLOCK + warp;   // adjacent pairs
    const int ib   = pair * 2;
    const int idx  = v * NPAIRS + pair;

    const float4* pp = g_pre + idx * 3;
    const float4 A0 = __ldg(pp + 0);
    const float4 A1 = __ldg(pp + 1);
    const float4 A2 = __ldg(pp + 2);
    const int    wn = __ldg(g_win + idx);

    const float q0 = A0.x, qs = A0.y, qp = A0.z, b0 = A0.w;
    const float bs = A1.x, bp = A1.y, alo_m = A1.z, blo = A1.w;
    const float ahi_m = A2.x, bhi = A2.y;
    const int   w0i     = wn & 0x3FF;
    const int   w1i     = (wn >> 10) & 0x3FF;
    const bool  drive_c = ((wn >> 20) & 1) != 0;
    const int   nslots  = (wn >> 21) & 0x7;

    float acc0 = 0.0f, acc1 = 0.0f;

    if (w0i <= w1i) {
        if (drive_c)
            walk_dispatch<C_, 1>(img, lane, w0i, w1i, nslots,
                                 q0, qs, qp, b0, bs, bp,
                                 alo_m, blo, ahi_m, bhi, acc0, acc1);
        else
            walk_dispatch<1, C_>(img, lane, w0i, w1i, nslots,
                                 q0, qs, qp, b0, bs, bp,
                                 alo_m, blo, ahi_m, bhi, acc0, acc1);
    }

    #pragma unroll
    for (int off = 16; off > 0; off >>= 1) {
        acc0 += __shfl_xor_sync(0xffffffffu, acc0, off);
        acc1 += __shfl_xor_sync(0xffffffffu, acc1, off);
    }

    if (lane == 0) {
        sino[v*NCOLS_ + ib]     = acc0;
        sino[v*NCOLS_ + ib + 1] = acc1;
    }
}

extern "C" void kernel_launch(void* const* d_in, const int* in_sizes, int n_in,
                              void* d_out, int out_size)
{
    const float* img    = (const float*)d_in[0];
    const float* src    = (const float*)d_in[1];
    const float* detc   = (const float*)d_in[2];
    const float* u      = (const float*)d_in[3];
    const float* center = (const float*)d_in[4];
    const float* cdir   = (const float*)d_in[5];
    float* sino = (float*)d_out;

    setup_kernel<<<(NWORK + 255) / 256, 256>>>(src, detc, u, center, cdir);

    dim3 grid(NPAIRS / WARPS_PER_BLOCK, V_);
    dim3 block(32 * WARPS_PER_BLOCK);
    fanbeam_fp_kernel<<<grid, block>>>(img, sino);
}